// round 4
// baseline (speedup 1.0000x reference)
#include <cuda_runtime.h>
#include <math.h>

#define Nn 4096
#define Dd 512
#define D3 1536
#define Ee 131072
#define MAXNB 128
#define HEADS 8
#define HD 64

// ---------------- scratch (device globals; referenced ONLY from device code) ----------------
__device__ __align__(128) int   g_winner[Nn * Nn];     // last-write-wins edge id per (dst,src)
__device__ __align__(128) int   g_cnt[Nn];
__device__ __align__(128) int   g_cols[Nn * MAXNB];
__device__ __align__(128) float g_wts[Nn * MAXNB];
__device__ __align__(128) float g_qkv[Nn * D3];        // q|k|v concatenated per row
__device__ __align__(128) float g_attn[Nn * Dd];
__device__ __align__(128) float g_tmp[Nn * Dd];
__device__ __align__(128) float g_h1[Nn * Dd];
__device__ int g_is64;

// ---------------- edge dtype detection + access ----------------
// Indices are all < 4096. If the buffer is int64, every odd 32-bit word (high
// halves) is 0. If int32, odd words are edge indices (nonzero w.p. ~1-4096^-4).
__global__ void k_detect_dtype(const void* ei) {
    const unsigned* w = (const unsigned*)ei;
    g_is64 = (w[1] == 0u && w[3] == 0u && w[5] == 0u && w[7] == 0u) ? 1 : 0;
}

__device__ __forceinline__ int2 load_edge(const void* ei, int e) {
    int2 r;
    if (g_is64) {
        const long long* p = (const long long*)ei;
        r.x = (int)p[e];        // src
        r.y = (int)p[Ee + e];   // dst
    } else {
        const int* p = (const int*)ei;
        r.x = p[e];
        r.y = p[Ee + e];
    }
    return r;
}

// ---------------- adjacency build ----------------
__global__ void k_init_winner() {
    int i = blockIdx.x * blockDim.x + threadIdx.x;   // one int4 per thread
    ((int4*)g_winner)[i] = make_int4(-1, -1, -1, -1);
}

__global__ void k_zero_cnt() {
    int i = blockIdx.x * blockDim.x + threadIdx.x;
    if (i < Nn) g_cnt[i] = 0;
}

__global__ void k_scatter_winner(const void* __restrict__ ei) {
    int e = blockIdx.x * blockDim.x + threadIdx.x;
    if (e >= Ee) return;
    int2 sd = load_edge(ei, e);
    if ((unsigned)sd.x >= Nn || (unsigned)sd.y >= Nn) return;  // safety
    atomicMax(&g_winner[sd.y * Nn + sd.x], e);
}

__global__ void k_append_self() {
    int i = blockIdx.x * blockDim.x + threadIdx.x;
    if (i >= Nn) return;
    if (g_winner[i * Nn + i] < 0) {      // diagonal not overridden by an edge
        int s = atomicAdd(&g_cnt[i], 1);
        if (s < MAXNB) { g_cols[i * MAXNB + s] = i; g_wts[i * MAXNB + s] = 0.0f; }
    }
}

__global__ void k_append_edges(const void* __restrict__ ei, const float* __restrict__ ew) {
    int e = blockIdx.x * blockDim.x + threadIdx.x;
    if (e >= Ee) return;
    int2 sd = load_edge(ei, e);
    if ((unsigned)sd.x >= Nn || (unsigned)sd.y >= Nn) return;  // safety
    if (g_winner[sd.y * Nn + sd.x] == e) { // surviving write for (dst,src)
        int s = atomicAdd(&g_cnt[sd.y], 1);
        if (s < MAXNB) { g_cols[sd.y * MAXNB + s] = sd.x; g_wts[sd.y * MAXNB + s] = ew[e]; }
    }
}

// ---------------- SGEMM: C[M,N] = A[M,K] * B[N,K]^T + bias[N] ----------------
// MODE 0: A = x (arg),  C = g_qkv,  N = D3
// MODE 1: A = g_attn,   C = g_tmp,  N = Dd
// MODE 2: A = g_h1,     C = g_tmp,  N = Dd
#define BM 128
#define BN 128
#define BK 8

template<int MODE>
__global__ __launch_bounds__(256) void sgemm_nt(
    const float* __restrict__ Ax,
    const float* __restrict__ B,
    const float* __restrict__ bias)
{
    constexpr int N = (MODE == 0) ? D3 : Dd;
    constexpr int K = Dd;
    const float* A = (MODE == 0) ? Ax : ((MODE == 1) ? (const float*)g_attn : (const float*)g_h1);
    float*       C = (MODE == 0) ? (float*)g_qkv : (float*)g_tmp;

    __shared__ float As[BK][BM];
    __shared__ float Bs[BK][BN];

    int tid = threadIdx.x;
    int rowBase = blockIdx.y * BM;
    int colBase = blockIdx.x * BN;

    int la_row = tid >> 1;            // 0..127
    int la_k   = (tid & 1) * 4;       // 0 or 4
    const float* Aptr = A + (size_t)(rowBase + la_row) * K + la_k;
    const float* Bptr = B + (size_t)(colBase + la_row) * K + la_k;

    int tx = tid & 15;                // col group 0..15
    int ty = tid >> 4;                // row group 0..15

    float acc[8][8];
    #pragma unroll
    for (int i = 0; i < 8; i++)
        #pragma unroll
        for (int j = 0; j < 8; j++) acc[i][j] = 0.0f;

    float4 aReg = *(const float4*)Aptr;
    float4 bReg = *(const float4*)Bptr;

    for (int k0 = 0; k0 < K; k0 += BK) {
        As[la_k + 0][la_row] = aReg.x;
        As[la_k + 1][la_row] = aReg.y;
        As[la_k + 2][la_row] = aReg.z;
        As[la_k + 3][la_row] = aReg.w;
        Bs[la_k + 0][la_row] = bReg.x;
        Bs[la_k + 1][la_row] = bReg.y;
        Bs[la_k + 2][la_row] = bReg.z;
        Bs[la_k + 3][la_row] = bReg.w;
        __syncthreads();

        if (k0 + BK < K) {
            aReg = *(const float4*)(Aptr + k0 + BK);
            bReg = *(const float4*)(Bptr + k0 + BK);
        }

        #pragma unroll
        for (int kk = 0; kk < BK; kk++) {
            float a[8], b[8];
            *(float4*)&a[0] = *(const float4*)&As[kk][ty * 8 + 0];
            *(float4*)&a[4] = *(const float4*)&As[kk][ty * 8 + 4];
            *(float4*)&b[0] = *(const float4*)&Bs[kk][tx * 8 + 0];
            *(float4*)&b[4] = *(const float4*)&Bs[kk][tx * 8 + 4];
            #pragma unroll
            for (int i = 0; i < 8; i++)
                #pragma unroll
                for (int j = 0; j < 8; j++)
                    acc[i][j] += a[i] * b[j];
        }
        __syncthreads();
    }

    #pragma unroll
    for (int i = 0; i < 8; i++) {
        int r = rowBase + ty * 8 + i;
        float* Crow = C + (size_t)r * N + colBase + tx * 8;
        const float* brow = bias + colBase + tx * 8;
        #pragma unroll
        for (int j = 0; j < 8; j++)
            Crow[j] = acc[i][j] + brow[j];
    }
}

// ---------------- sparse attention: one block per query row, one warp per head ----------------
__global__ __launch_bounds__(256) void sparse_attn() {
    int i = blockIdx.x;
    int h = threadIdx.x >> 5;
    int lane = threadIdx.x & 31;
    int cnt = g_cnt[i];
    if (cnt > MAXNB) cnt = MAXNB;

    __shared__ float sc[HEADS][MAXNB];
    __shared__ int   cols_s[MAXNB];
    __shared__ float wts_s[MAXNB];

    for (int t = threadIdx.x; t < cnt; t += 256) {
        cols_s[t] = g_cols[i * MAXNB + t];
        wts_s[t]  = g_wts[i * MAXNB + t];
    }
    __syncthreads();

    // q for this head: 64 floats -> 2 per lane
    float2 qv = *(const float2*)(g_qkv + (size_t)i * D3 + h * HD + lane * 2);

    // pass 1: scores
    for (int t = 0; t < cnt; t++) {
        int j = cols_s[t];
        float2 kv = *(const float2*)(g_qkv + (size_t)j * D3 + Dd + h * HD + lane * 2);
        float d = qv.x * kv.x + qv.y * kv.y;
        #pragma unroll
        for (int o = 16; o; o >>= 1) d += __shfl_xor_sync(0xffffffffu, d, o);
        if (lane == 0) sc[h][t] = d * 0.125f + wts_s[t];
    }
    __syncwarp();

    // softmax over cnt entries
    float m = -1e30f;
    for (int t = lane; t < cnt; t += 32) m = fmaxf(m, sc[h][t]);
    #pragma unroll
    for (int o = 16; o; o >>= 1) m = fmaxf(m, __shfl_xor_sync(0xffffffffu, m, o));

    float s = 0.0f;
    for (int t = lane; t < cnt; t += 32) {
        float e = expf(sc[h][t] - m);
        sc[h][t] = e;
        s += e;
    }
    #pragma unroll
    for (int o = 16; o; o >>= 1) s += __shfl_xor_sync(0xffffffffu, s, o);
    float inv = 1.0f / s;
    __syncwarp();

    // weighted V accumulation
    float2 acc = make_float2(0.0f, 0.0f);
    for (int t = 0; t < cnt; t++) {
        float p = sc[h][t] * inv;
        int j = cols_s[t];
        float2 vv = *(const float2*)(g_qkv + (size_t)j * D3 + 2 * Dd + h * HD + lane * 2);
        acc.x += p * vv.x;
        acc.y += p * vv.y;
    }
    float* op = g_attn + (size_t)i * Dd + h * HD + lane * 2;
    op[0] = acc.x;
    op[1] = acc.y;
}

// ---------------- add + LayerNorm ----------------
// MODE 0: out = LN(x_arg + g_tmp) -> g_h1
// MODE 1: out = LN(g_h1 + g_tmp)  -> out_ext
template<int MODE>
__global__ __launch_bounds__(256) void add_ln(
    const float* __restrict__ a_in,
    const float* __restrict__ g, const float* __restrict__ be,
    float* __restrict__ out_ext)
{
    const float* a = (MODE == 0) ? a_in : (const float*)g_h1;
    const float* b = (const float*)g_tmp;
    float*       o = (MODE == 0) ? (float*)g_h1 : out_ext;

    int i = blockIdx.x;
    int t = threadIdx.x;
    int lane = t & 31, w = t >> 5;
    __shared__ float sh[8];

    float2 av = *(const float2*)(a + (size_t)i * Dd + t * 2);
    float2 bv = *(const float2*)(b + (size_t)i * Dd + t * 2);
    float yx = av.x + bv.x;
    float yy = av.y + bv.y;

    // mean
    float s = yx + yy;
    #pragma unroll
    for (int oo = 16; oo; oo >>= 1) s += __shfl_xor_sync(0xffffffffu, s, oo);
    if (lane == 0) sh[w] = s;
    __syncthreads();
    if (t == 0) {
        float tot = 0;
        #pragma unroll
        for (int k = 0; k < 8; k++) tot += sh[k];
        sh[0] = tot;
    }
    __syncthreads();
    float mu = sh[0] * (1.0f / Dd);
    __syncthreads();

    // variance
    float dx = yx - mu, dy = yy - mu;
    float q = dx * dx + dy * dy;
    #pragma unroll
    for (int oo = 16; oo; oo >>= 1) q += __shfl_xor_sync(0xffffffffu, q, oo);
    if (lane == 0) sh[w] = q;
    __syncthreads();
    if (t == 0) {
        float tot = 0;
        #pragma unroll
        for (int k = 0; k < 8; k++) tot += sh[k];
        sh[0] = tot;
    }
    __syncthreads();
    float var = sh[0] * (1.0f / Dd);
    float r = rsqrtf(var + 1e-5f);

    float2 gv  = *(const float2*)(g + t * 2);
    float2 bev = *(const float2*)(be + t * 2);
    float2 o2;
    o2.x = dx * r * gv.x + bev.x;
    o2.y = dy * r * gv.y + bev.y;
    *(float2*)(o + (size_t)i * Dd + t * 2) = o2;
}

// ---------------- launch (kernel launches ONLY; no runtime API calls) ----------------
extern "C" void kernel_launch(void* const* d_in, const int* in_sizes, int n_in,
                              void* d_out, int out_size) {
    const float* x    = (const float*)d_in[0];
    const void*  ei   = d_in[1];                    // int32 or int64, auto-detected
    const float* ew   = (const float*)d_in[2];
    const float* Wqkv = (const float*)d_in[3];
    const float* bqkv = (const float*)d_in[4];
    const float* Wo   = (const float*)d_in[5];
    const float* bo   = (const float*)d_in[6];
    const float* W1   = (const float*)d_in[7];
    const float* b1   = (const float*)d_in[8];
    const float* g1   = (const float*)d_in[9];
    const float* be1  = (const float*)d_in[10];
    const float* g2   = (const float*)d_in[11];
    const float* be2  = (const float*)d_in[12];
    float* out = (float*)d_out;

    // 0) detect edge_index dtype (int32 vs int64)
    k_detect_dtype<<<1, 1>>>(ei);

    // 1) adjacency with exact last-write-wins dedup
    k_init_winner<<<(Nn * Nn / 4) / 256, 256>>>();
    k_zero_cnt<<<(Nn + 255) / 256, 256>>>();
    k_scatter_winner<<<Ee / 256, 256>>>(ei);
    k_append_self<<<(Nn + 255) / 256, 256>>>();
    k_append_edges<<<Ee / 256, 256>>>(ei, ew);

    // 2) qkv = x @ Wqkv^T + bqkv            -> g_qkv
    sgemm_nt<0><<<dim3(D3 / BN, Nn / BM), 256>>>(x, Wqkv, bqkv);

    // 3) sparse multi-head attention        -> g_attn
    sparse_attn<<<Nn, 256>>>();

    // 4) attn_out = g_attn @ Wo^T + bo      -> g_tmp
    sgemm_nt<1><<<dim3(Dd / BN, Nn / BM), 256>>>(nullptr, Wo, bo);

    // 5) h1 = LN(x + g_tmp)                 -> g_h1
    add_ln<0><<<Nn, 256>>>(x, g1, be1, out);

    // 6) ffn = g_h1 @ W1^T + b1             -> g_tmp
    sgemm_nt<2><<<dim3(Dd / BN, Nn / BM), 256>>>(nullptr, W1, b1);

    // 7) out = LN(g_h1 + g_tmp)             -> out
    add_ln<1><<<Nn, 256>>>(nullptr, g2, be2, out);
}

// round 5
// speedup vs baseline: 1.6737x; 1.6737x over previous
#include <cuda_runtime.h>
#include <math.h>
#include <stdint.h>

#define Nn 4096
#define Dd 512
#define D3 1536
#define Ee 131072
#define MAXNB 128
#define HEADS 8
#define HD 64

// ---------------- scratch (device globals; referenced ONLY from device code) ----------------
__device__ int   g_winner[Nn * Nn];     // 0 = empty; else edge_id+1 (zero-init, self-restoring)
__device__ __align__(128) int   g_cnt[Nn];
__device__ __align__(128) int   g_cols[Nn * MAXNB];
__device__ __align__(128) float g_wts[Nn * MAXNB];
__device__ __align__(128) float g_qkv[Nn * D3];        // q|k|v concatenated per row
__device__ __align__(128) float g_attn[Nn * Dd];
__device__ __align__(128) float g_tmp[Nn * Dd];
__device__ __align__(128) float g_h1[Nn * Dd];
__device__ int g_is64;

// ---------------- edge dtype detection + access ----------------
__global__ void k_detect_dtype(const void* ei) {
    const unsigned* w = (const unsigned*)ei;
    g_is64 = (w[1] == 0u && w[3] == 0u && w[5] == 0u && w[7] == 0u) ? 1 : 0;
}

__device__ __forceinline__ int2 load_edge(const void* ei, int e) {
    int2 r;
    if (g_is64) {
        const long long* p = (const long long*)ei;
        r.x = (int)p[e];        // src
        r.y = (int)p[Ee + e];   // dst
    } else {
        const int* p = (const int*)ei;
        r.x = p[e];
        r.y = p[Ee + e];
    }
    return r;
}

// ---------------- adjacency build (winner grid: 0 = empty, else e+1) ----------------
__global__ void k_zero_cnt() {
    int i = blockIdx.x * blockDim.x + threadIdx.x;
    if (i < Nn) g_cnt[i] = 0;
}

__global__ void k_scatter_winner(const void* __restrict__ ei) {
    int e = blockIdx.x * blockDim.x + threadIdx.x;
    if (e >= Ee) return;
    int2 sd = load_edge(ei, e);
    if ((unsigned)sd.x >= Nn || (unsigned)sd.y >= Nn) return;
    atomicMax(&g_winner[sd.y * Nn + sd.x], e + 1);
}

__global__ void k_append_self() {
    int i = blockIdx.x * blockDim.x + threadIdx.x;
    if (i >= Nn) return;
    if (g_winner[i * Nn + i] == 0) {     // diagonal not overridden by an edge
        int s = atomicAdd(&g_cnt[i], 1);
        if (s < MAXNB) { g_cols[i * MAXNB + s] = i; g_wts[i * MAXNB + s] = 0.0f; }
    }
}

__global__ void k_append_edges(const void* __restrict__ ei, const float* __restrict__ ew) {
    int e = blockIdx.x * blockDim.x + threadIdx.x;
    if (e >= Ee) return;
    int2 sd = load_edge(ei, e);
    if ((unsigned)sd.x >= Nn || (unsigned)sd.y >= Nn) return;
    if (g_winner[sd.y * Nn + sd.x] == e + 1) {   // surviving write for (dst,src)
        int s = atomicAdd(&g_cnt[sd.y], 1);
        if (s < MAXNB) { g_cols[sd.y * MAXNB + s] = sd.x; g_wts[sd.y * MAXNB + s] = ew[e]; }
    }
}

__global__ void k_cleanup_winner(const void* __restrict__ ei) {
    int e = blockIdx.x * blockDim.x + threadIdx.x;
    if (e >= Ee) return;
    int2 sd = load_edge(ei, e);
    if ((unsigned)sd.x >= Nn || (unsigned)sd.y >= Nn) return;
    g_winner[sd.y * Nn + sd.x] = 0;      // restore zero-state for next replay
}

// ---------------- tf32 tensor-core GEMM: C[M,N] = A[M,K] * B[N,K]^T + bias[N] ----------------
// MODE 0: A = x (arg),  C = g_qkv,  N = D3
// MODE 1: A = g_attn,   C = g_tmp,  N = Dd
// MODE 2: A = g_h1,     C = g_tmp,  N = Dd
#define BM 128
#define BN 128
#define BKK 16
#define SPAD 20   // smem row stride in 32-bit words (conflict-free fragment loads)

__device__ __forceinline__ uint32_t f2tf(float f) {
    uint32_t u;
    asm("cvt.rna.tf32.f32 %0, %1;" : "=r"(u) : "f"(f));
    return u;
}

__device__ __forceinline__ void mma8(float* c, const uint32_t* a, const uint32_t* b) {
    asm volatile(
        "mma.sync.aligned.m16n8k8.row.col.f32.tf32.tf32.f32 "
        "{%0,%1,%2,%3},{%4,%5,%6,%7},{%8,%9},{%0,%1,%2,%3};"
        : "+f"(c[0]), "+f"(c[1]), "+f"(c[2]), "+f"(c[3])
        : "r"(a[0]), "r"(a[1]), "r"(a[2]), "r"(a[3]), "r"(b[0]), "r"(b[1]));
}

template<int MODE>
__global__ __launch_bounds__(256) void mma_gemm(
    const float* __restrict__ Ax,
    const float* __restrict__ B,
    const float* __restrict__ bias)
{
    constexpr int N = (MODE == 0) ? D3 : Dd;
    constexpr int K = Dd;
    const float* A = (MODE == 0) ? Ax : ((MODE == 1) ? (const float*)g_attn : (const float*)g_h1);
    float*       C = (MODE == 0) ? (float*)g_qkv : (float*)g_tmp;

    __shared__ uint32_t As[BM * SPAD];
    __shared__ uint32_t Bs[BN * SPAD];

    int tid  = threadIdx.x;
    int lane = tid & 31;
    int warp = tid >> 5;
    int wRow = (warp >> 2) * 64;       // 0 or 64
    int wCol = (warp & 3) * 32;        // 0,32,64,96
    int g  = lane >> 2;                // 0..7
    int t4 = lane & 3;                 // 0..3

    int rowBase = blockIdx.y * BM;
    int colBase = blockIdx.x * BN;

    // global staging: each thread loads 2 float4 from A and B per k-slab
    int ldRow = tid >> 1;              // 0..127
    int ldCol = (tid & 1) * 8;         // 0 or 8
    const float* Ag = A + (size_t)(rowBase + ldRow) * K + ldCol;
    const float* Bg = B + (size_t)(colBase + ldRow) * K + ldCol;
    uint32_t* AsW = As + ldRow * SPAD + ldCol;
    uint32_t* BsW = Bs + ldRow * SPAD + ldCol;

    float c[16][4];
    #pragma unroll
    for (int i = 0; i < 16; i++)
        #pragma unroll
        for (int j = 0; j < 4; j++) c[i][j] = 0.0f;

    float4 pa0 = *(const float4*)(Ag);
    float4 pa1 = *(const float4*)(Ag + 4);
    float4 pb0 = *(const float4*)(Bg);
    float4 pb1 = *(const float4*)(Bg + 4);

    for (int k0 = 0; k0 < K; k0 += BKK) {
        uint4 ua0 = make_uint4(f2tf(pa0.x), f2tf(pa0.y), f2tf(pa0.z), f2tf(pa0.w));
        uint4 ua1 = make_uint4(f2tf(pa1.x), f2tf(pa1.y), f2tf(pa1.z), f2tf(pa1.w));
        uint4 ub0 = make_uint4(f2tf(pb0.x), f2tf(pb0.y), f2tf(pb0.z), f2tf(pb0.w));
        uint4 ub1 = make_uint4(f2tf(pb1.x), f2tf(pb1.y), f2tf(pb1.z), f2tf(pb1.w));
        *(uint4*)(AsW)     = ua0;
        *(uint4*)(AsW + 4) = ua1;
        *(uint4*)(BsW)     = ub0;
        *(uint4*)(BsW + 4) = ub1;
        __syncthreads();

        if (k0 + BKK < K) {
            pa0 = *(const float4*)(Ag + k0 + BKK);
            pa1 = *(const float4*)(Ag + k0 + BKK + 4);
            pb0 = *(const float4*)(Bg + k0 + BKK);
            pb1 = *(const float4*)(Bg + k0 + BKK + 4);
        }

        #pragma unroll
        for (int ks = 0; ks < BKK; ks += 8) {
            uint32_t af[4][4], bf[4][2];
            #pragma unroll
            for (int mt = 0; mt < 4; mt++) {
                int rb = wRow + mt * 16;
                af[mt][0] = As[(rb + g) * SPAD + ks + t4];
                af[mt][1] = As[(rb + g + 8) * SPAD + ks + t4];
                af[mt][2] = As[(rb + g) * SPAD + ks + t4 + 4];
                af[mt][3] = As[(rb + g + 8) * SPAD + ks + t4 + 4];
            }
            #pragma unroll
            for (int nt = 0; nt < 4; nt++) {
                int cb = wCol + nt * 8;
                bf[nt][0] = Bs[(cb + g) * SPAD + ks + t4];
                bf[nt][1] = Bs[(cb + g) * SPAD + ks + t4 + 4];
            }
            #pragma unroll
            for (int mt = 0; mt < 4; mt++)
                #pragma unroll
                for (int nt = 0; nt < 4; nt++)
                    mma8(c[mt * 4 + nt], af[mt], bf[nt]);
        }
        __syncthreads();
    }

    // epilogue: c0/c1 at (row g, cols 2*t4, 2*t4+1); c2/c3 at row g+8
    #pragma unroll
    for (int mt = 0; mt < 4; mt++) {
        #pragma unroll
        for (int nt = 0; nt < 4; nt++) {
            float* cf = c[mt * 4 + nt];
            int r  = rowBase + wRow + mt * 16 + g;
            int cc = colBase + wCol + nt * 8 + t4 * 2;
            float bx = bias[cc], by = bias[cc + 1];
            float2 v0 = make_float2(cf[0] + bx, cf[1] + by);
            float2 v1 = make_float2(cf[2] + bx, cf[3] + by);
            *(float2*)(C + (size_t)r * N + cc)       = v0;
            *(float2*)(C + (size_t)(r + 8) * N + cc) = v1;
        }
    }
}

// ---------------- sparse attention: one block per query row, one warp per head ----------------
__global__ __launch_bounds__(256) void sparse_attn() {
    int i = blockIdx.x;
    int h = threadIdx.x >> 5;
    int lane = threadIdx.x & 31;
    int cnt = g_cnt[i];
    if (cnt > MAXNB) cnt = MAXNB;

    __shared__ float sc[HEADS][MAXNB];
    __shared__ int   cols_s[MAXNB];
    __shared__ float wts_s[MAXNB];

    for (int t = threadIdx.x; t < cnt; t += 256) {
        cols_s[t] = g_cols[i * MAXNB + t];
        wts_s[t]  = g_wts[i * MAXNB + t];
    }
    __syncthreads();

    float2 qv = *(const float2*)(g_qkv + (size_t)i * D3 + h * HD + lane * 2);

    for (int t = 0; t < cnt; t++) {
        int j = cols_s[t];
        float2 kv = *(const float2*)(g_qkv + (size_t)j * D3 + Dd + h * HD + lane * 2);
        float d = qv.x * kv.x + qv.y * kv.y;
        #pragma unroll
        for (int o = 16; o; o >>= 1) d += __shfl_xor_sync(0xffffffffu, d, o);
        if (lane == 0) sc[h][t] = d * 0.125f + wts_s[t];
    }
    __syncwarp();

    float m = -1e30f;
    for (int t = lane; t < cnt; t += 32) m = fmaxf(m, sc[h][t]);
    #pragma unroll
    for (int o = 16; o; o >>= 1) m = fmaxf(m, __shfl_xor_sync(0xffffffffu, m, o));

    float s = 0.0f;
    for (int t = lane; t < cnt; t += 32) {
        float e = expf(sc[h][t] - m);
        sc[h][t] = e;
        s += e;
    }
    #pragma unroll
    for (int o = 16; o; o >>= 1) s += __shfl_xor_sync(0xffffffffu, s, o);
    float inv = 1.0f / s;
    __syncwarp();

    float2 acc = make_float2(0.0f, 0.0f);
    for (int t = 0; t < cnt; t++) {
        float p = sc[h][t] * inv;
        int j = cols_s[t];
        float2 vv = *(const float2*)(g_qkv + (size_t)j * D3 + 2 * Dd + h * HD + lane * 2);
        acc.x += p * vv.x;
        acc.y += p * vv.y;
    }
    float* op = g_attn + (size_t)i * Dd + h * HD + lane * 2;
    op[0] = acc.x;
    op[1] = acc.y;
}

// ---------------- add + LayerNorm ----------------
// MODE 0: g_h1 = LN(x_arg + g_tmp);  MODE 1: out_ext = LN(g_h1 + g_tmp)
template<int MODE>
__global__ __launch_bounds__(256) void add_ln(
    const float* __restrict__ a_in,
    const float* __restrict__ g, const float* __restrict__ be,
    float* __restrict__ out_ext)
{
    const float* a = (MODE == 0) ? a_in : (const float*)g_h1;
    const float* b = (const float*)g_tmp;
    float*       o = (MODE == 0) ? (float*)g_h1 : out_ext;

    int i = blockIdx.x;
    int t = threadIdx.x;
    int lane = t & 31, w = t >> 5;
    __shared__ float sh[8];

    float2 av = *(const float2*)(a + (size_t)i * Dd + t * 2);
    float2 bv = *(const float2*)(b + (size_t)i * Dd + t * 2);
    float yx = av.x + bv.x;
    float yy = av.y + bv.y;

    float s = yx + yy;
    #pragma unroll
    for (int oo = 16; oo; oo >>= 1) s += __shfl_xor_sync(0xffffffffu, s, oo);
    if (lane == 0) sh[w] = s;
    __syncthreads();
    if (t == 0) {
        float tot = 0;
        #pragma unroll
        for (int k = 0; k < 8; k++) tot += sh[k];
        sh[0] = tot;
    }
    __syncthreads();
    float mu = sh[0] * (1.0f / Dd);
    __syncthreads();

    float dx = yx - mu, dy = yy - mu;
    float q = dx * dx + dy * dy;
    #pragma unroll
    for (int oo = 16; oo; oo >>= 1) q += __shfl_xor_sync(0xffffffffu, q, oo);
    if (lane == 0) sh[w] = q;
    __syncthreads();
    if (t == 0) {
        float tot = 0;
        #pragma unroll
        for (int k = 0; k < 8; k++) tot += sh[k];
        sh[0] = tot;
    }
    __syncthreads();
    float var = sh[0] * (1.0f / Dd);
    float r = rsqrtf(var + 1e-5f);

    float2 gv  = *(const float2*)(g + t * 2);
    float2 bev = *(const float2*)(be + t * 2);
    float2 o2;
    o2.x = dx * r * gv.x + bev.x;
    o2.y = dy * r * gv.y + bev.y;
    *(float2*)(o + (size_t)i * Dd + t * 2) = o2;
}

// ---------------- launch (kernel launches ONLY) ----------------
extern "C" void kernel_launch(void* const* d_in, const int* in_sizes, int n_in,
                              void* d_out, int out_size) {
    const float* x    = (const float*)d_in[0];
    const void*  ei   = d_in[1];
    const float* ew   = (const float*)d_in[2];
    const float* Wqkv = (const float*)d_in[3];
    const float* bqkv = (const float*)d_in[4];
    const float* Wo   = (const float*)d_in[5];
    const float* bo   = (const float*)d_in[6];
    const float* W1   = (const float*)d_in[7];
    const float* b1   = (const float*)d_in[8];
    const float* g1   = (const float*)d_in[9];
    const float* be1  = (const float*)d_in[10];
    const float* g2   = (const float*)d_in[11];
    const float* be2  = (const float*)d_in[12];
    float* out = (float*)d_out;

    // 0) dtype detect + adjacency (winner grid self-restores to zero)
    k_detect_dtype<<<1, 1>>>(ei);
    k_zero_cnt<<<(Nn + 255) / 256, 256>>>();
    k_scatter_winner<<<Ee / 256, 256>>>(ei);
    k_append_self<<<(Nn + 255) / 256, 256>>>();
    k_append_edges<<<Ee / 256, 256>>>(ei, ew);
    k_cleanup_winner<<<Ee / 256, 256>>>(ei);

    // 1) qkv = x @ Wqkv^T + bqkv            -> g_qkv
    mma_gemm<0><<<dim3(D3 / BN, Nn / BM), 256>>>(x, Wqkv, bqkv);

    // 2) sparse multi-head attention        -> g_attn
    sparse_attn<<<Nn, 256>>>();

    // 3) attn_out = g_attn @ Wo^T + bo      -> g_tmp
    mma_gemm<1><<<dim3(Dd / BN, Nn / BM), 256>>>(nullptr, Wo, bo);

    // 4) h1 = LN(x + g_tmp)                 -> g_h1
    add_ln<0><<<Nn, 256>>>(x, g1, be1, out);

    // 5) ffn = g_h1 @ W1^T + b1             -> g_tmp
    mma_gemm<2><<<dim3(Dd / BN, Nn / BM), 256>>>(nullptr, W1, b1);

    // 6) out = LN(g_h1 + g_tmp)             -> out
    add_ln<1><<<Nn, 256>>>(nullptr, g2, be2, out);
}